// round 14
// baseline (speedup 1.0000x reference)
#include <cuda_runtime.h>
#include <cuda_fp16.h>
#include <math.h>

#define N_NODES 100000
#define N_EDGES 1250000
#define D 64
#define N_LAYERS 4

// ---- gemm kernel config ----
#define TPB 256                       // 8 warps, 1 M-tile (16 nodes) each
#define NPB 128                       // nodes per block
#define A_PITCH 136                   // halves; 272B row stride -> conflict-free LDSM
#define W_PITCH 72                    // halves; 144B row stride -> conflict-free LDSM
#define SA_HALVES (NPB * A_PITCH)     // 17408
#define SW_HALVES (128 * W_PITCH)     // 9216
#define SMEM_BYTES ((SA_HALVES + SW_HALVES) * 2 + D * 4)

// ---- gather kernel config ----
#define GTPB 256
#define GNPB 32

// ---- scan config ----
#define SBLK 1024
#define NSB ((N_NODES + SBLK - 1) / SBLK)   // 98 blocks <= 148 SMs: lookback safe

// ---- edge-kernel grid (4 edges per thread; N_EDGES % 4 == 0) ----
#define EBLOCKS ((N_EDGES / 4 + 255) / 256)   // 1221
#define ETHREADS (EBLOCKS * 256)              // 312576

// ---------------- scratch (static device globals; zero-init at load) ---------
__device__ __half g_x16[N_NODES * D];
__device__ __half g_h16a[N_NODES * D];
__device__ __half g_h16b[N_NODES * D];
__device__ __half g_agg16[N_NODES * D];
__device__ int    g_counts[N_NODES];          // invariant: all-zero at call entry
__device__ int    g_rowptr[N_NODES + 1];
__device__ int    g_rank[N_EDGES];            // within-segment rank per edge
__device__ int    g_csr[N_EDGES];
__device__ unsigned long long g_bstat[NSB];   // lookback: flag<<32 | value
__device__ int    g_is64;

// ---------------- mma helpers ------------------------------------------------
__device__ __forceinline__ unsigned s2u(const void* p) {
    return (unsigned)__cvta_generic_to_shared(p);
}
__device__ __forceinline__ void ldmx4(unsigned& a0, unsigned& a1,
                                      unsigned& a2, unsigned& a3, unsigned addr) {
    asm volatile("ldmatrix.sync.aligned.m8n8.x4.shared.b16 {%0,%1,%2,%3}, [%4];"
                 : "=r"(a0), "=r"(a1), "=r"(a2), "=r"(a3) : "r"(addr));
}
__device__ __forceinline__ void ldmx2t(unsigned& b0, unsigned& b1, unsigned addr) {
    asm volatile("ldmatrix.sync.aligned.m8n8.x2.trans.shared.b16 {%0,%1}, [%2];"
                 : "=r"(b0), "=r"(b1) : "r"(addr));
}
__device__ __forceinline__ void mma16816(float* c, unsigned a0, unsigned a1,
                                         unsigned a2, unsigned a3,
                                         unsigned b0, unsigned b1) {
    asm volatile(
        "mma.sync.aligned.m16n8k16.row.col.f32.f16.f16.f32 "
        "{%0,%1,%2,%3}, {%4,%5,%6,%7}, {%8,%9}, {%0,%1,%2,%3};"
        : "+f"(c[0]), "+f"(c[1]), "+f"(c[2]), "+f"(c[3])
        : "r"(a0), "r"(a1), "r"(a2), "r"(a3), "r"(b0), "r"(b1));
}

// ---------------- edge load helper (4 edges) ----------------------------------
__device__ __forceinline__ void load4(const void* edge_raw, int p, int base_ll2,
                                      int base_i4, int& a, int& b, int& c, int& d,
                                      int is64) {
    if (is64) {
        longlong2 v0 = ((const longlong2*)edge_raw)[base_ll2 + 2 * p];
        longlong2 v1 = ((const longlong2*)edge_raw)[base_ll2 + 2 * p + 1];
        a = (int)v0.x; b = (int)v0.y; c = (int)v1.x; d = (int)v1.y;
    } else {
        int4 v = ((const int4*)edge_raw)[base_i4 + p];
        a = v.x; b = v.y; c = v.z; d = v.w;
    }
}

// ---------------- init: dtype detect + zero lookback status (1 block) --------
__global__ void init_kernel(const void* __restrict__ edge_raw) {
    int i = threadIdx.x;
    if (i < NSB) g_bstat[i] = 0ull;
    if (i == 0) {
        const long long* e64 = (const long long*)edge_raw;
        int ok64 = 1;
        #pragma unroll 8
        for (int t = 0; t < 64; t++) {
            long long v = e64[t];
            if (v < 0 || v >= N_NODES) ok64 = 0;
        }
        g_is64 = ok64;
    }
}

// ---------------- histogram (+rank) + fused x->fp16 conversion ----------------
__global__ void histogram_kernel(const void* __restrict__ edge_raw,
                                 const float* __restrict__ x) {
    int p = blockIdx.x * blockDim.x + threadIdx.x;
    // fused conversion (grid-strided)
    #pragma unroll 1
    for (int i = p; i < N_NODES * D / 2; i += ETHREADS) {
        float2 v = ((const float2*)x)[i];
        ((__half2*)g_x16)[i] = __floats2half2_rn(v.x, v.y);
    }
    int e = p * 4;
    if (e >= N_EDGES) return;
    int d0, d1, d2, d3;
    load4(edge_raw, p, N_EDGES / 2, N_EDGES / 4, d0, d1, d2, d3, g_is64);
    int r0 = (d0 >= 0 && d0 < N_NODES) ? atomicAdd(&g_counts[d0], 1) : 0;
    int r1 = (d1 >= 0 && d1 < N_NODES) ? atomicAdd(&g_counts[d1], 1) : 0;
    int r2 = (d2 >= 0 && d2 < N_NODES) ? atomicAdd(&g_counts[d2], 1) : 0;
    int r3 = (d3 >= 0 && d3 < N_NODES) ? atomicAdd(&g_counts[d3], 1) : 0;
    int4 rv = make_int4(r0, r1, r2, r3);
    ((int4*)g_rank)[p] = rv;
}

// single-pass decoupled-lookback exclusive scan (warp-parallel lookback).
// Re-zeroes g_counts for the next call (module load guarantees first-call zero).
__global__ __launch_bounds__(SBLK) void scan_kernel() {
    __shared__ int wsum[32];
    __shared__ int sPrefix;
    int tid = threadIdx.x, lane = tid & 31, w = tid >> 5;
    int bid = blockIdx.x;
    int i = bid * SBLK + tid;
    int v = (i < N_NODES) ? g_counts[i] : 0;
    if (i < N_NODES) g_counts[i] = 0;         // restore invariant for next call

    int x = v;
    #pragma unroll
    for (int off = 1; off < 32; off <<= 1) {
        int y = __shfl_up_sync(0xffffffffu, x, off);
        if (lane >= off) x += y;
    }
    if (lane == 31) wsum[w] = x;
    __syncthreads();
    if (w == 0) {
        int s = wsum[lane];
        #pragma unroll
        for (int off = 1; off < 32; off <<= 1) {
            int y = __shfl_up_sync(0xffffffffu, s, off);
            if (lane >= off) s += y;
        }
        wsum[lane] = s;
    }
    __syncthreads();
    int incl = x + ((w > 0) ? wsum[w - 1] : 0);
    int total = wsum[31];                     // block aggregate

    if (w == 0) {                             // warp 0: publish + lookback
        int prefix = 0;
        if (bid > 0) {
            if (lane == 0)
                atomicExch(&g_bstat[bid], (1ull << 32) | (unsigned)total);
            int p = bid - 1;
            while (true) {
                int idx = p - lane;           // lane 0 = nearest predecessor
                unsigned long long s = (idx >= 0)
                    ? atomicAdd(&g_bstat[idx], 0ull) : (2ull << 32);
                unsigned flag = (unsigned)(s >> 32);
                if (!__all_sync(0xffffffffu, flag != 0u)) continue;  // retry window
                unsigned stopmask = __ballot_sync(0xffffffffu, flag == 2u);
                int firstStop = stopmask ? (__ffs(stopmask) - 1) : 32;
                int val = (idx >= 0 && lane <= firstStop) ? (int)(unsigned)s : 0;
                #pragma unroll
                for (int o = 16; o; o >>= 1)
                    val += __shfl_xor_sync(0xffffffffu, val, o);
                prefix += val;
                if (stopmask) break;
                p -= 32;
            }
        }
        if (lane == 0) {
            sPrefix = prefix;
            atomicExch(&g_bstat[bid], (2ull << 32) | (unsigned)(prefix + total));
        }
    }
    __syncthreads();
    int base = sPrefix;
    if (i < N_NODES) g_rowptr[i] = base + incl - v;
    if (bid == NSB - 1 && tid == 0) g_rowptr[N_NODES] = base + total;
}

// scatter via precomputed rank: pos = rowptr[dst] + rank[e]  (no atomics)
__global__ void scatter_kernel(const void* __restrict__ edge_raw) {
    int p = blockIdx.x * blockDim.x + threadIdx.x;
    int e = p * 4;
    if (e >= N_EDGES) return;
    int s0, s1, s2, s3, d0, d1, d2, d3;
    load4(edge_raw, p, 0, 0, s0, s1, s2, s3, g_is64);
    load4(edge_raw, p, N_EDGES / 2, N_EDGES / 4, d0, d1, d2, d3, g_is64);
    int4 rv = ((const int4*)g_rank)[p];
    if (s0 >= 0 && s0 < N_NODES && d0 >= 0 && d0 < N_NODES) {
        int pos = g_rowptr[d0] + rv.x;
        if (pos >= 0 && pos < N_EDGES) g_csr[pos] = s0;
    }
    if (s1 >= 0 && s1 < N_NODES && d1 >= 0 && d1 < N_NODES) {
        int pos = g_rowptr[d1] + rv.y;
        if (pos >= 0 && pos < N_EDGES) g_csr[pos] = s1;
    }
    if (s2 >= 0 && s2 < N_NODES && d2 >= 0 && d2 < N_NODES) {
        int pos = g_rowptr[d2] + rv.z;
        if (pos >= 0 && pos < N_EDGES) g_csr[pos] = s2;
    }
    if (s3 >= 0 && s3 < N_NODES && d3 >= 0 && d3 < N_NODES) {
        int pos = g_rowptr[d3] + rv.w;
        if (pos >= 0 && pos < N_EDGES) g_csr[pos] = s3;
    }
}

// ---------------- gather fp16: h16 -> agg16 ----------------------------------
#define GMAX2(v) do { \
    m0 = __hmax2(m0, *(__half2*)&(v).x); m1 = __hmax2(m1, *(__half2*)&(v).y); \
    m2 = __hmax2(m2, *(__half2*)&(v).z); m3 = __hmax2(m3, *(__half2*)&(v).w); } while (0)

__global__ __launch_bounds__(GTPB) void gather16_kernel(
    const __half* __restrict__ h_in, __half* __restrict__ agg_out)
{
    int tid = threadIdx.x;
    int warp = tid >> 5, lane = tid & 31;
    int sub = lane >> 3, dl = lane & 7;

    int node = blockIdx.x * GNPB + warp * 4 + sub;
    if (node >= N_NODES) return;
    int start = g_rowptr[node];
    int end   = g_rowptr[node + 1];

    const __half neginf = __ushort_as_half((unsigned short)0xFC00);
    __half2 m0 = __half2half2(neginf), m1 = m0, m2 = m0, m3 = m0;

    int j = start;
    #pragma unroll 1
    for (; j + 8 <= end; j += 8) {
        int s0 = g_csr[j],     s1 = g_csr[j + 1];
        int s2 = g_csr[j + 2], s3 = g_csr[j + 3];
        int s4 = g_csr[j + 4], s5 = g_csr[j + 5];
        int s6 = g_csr[j + 6], s7 = g_csr[j + 7];
        uint4 v0 = *(const uint4*)(h_in + (size_t)s0 * D + dl * 8);
        uint4 v1 = *(const uint4*)(h_in + (size_t)s1 * D + dl * 8);
        uint4 v2 = *(const uint4*)(h_in + (size_t)s2 * D + dl * 8);
        uint4 v3 = *(const uint4*)(h_in + (size_t)s3 * D + dl * 8);
        uint4 v4 = *(const uint4*)(h_in + (size_t)s4 * D + dl * 8);
        uint4 v5 = *(const uint4*)(h_in + (size_t)s5 * D + dl * 8);
        uint4 v6 = *(const uint4*)(h_in + (size_t)s6 * D + dl * 8);
        uint4 v7 = *(const uint4*)(h_in + (size_t)s7 * D + dl * 8);
        GMAX2(v0); GMAX2(v1); GMAX2(v2); GMAX2(v3);
        GMAX2(v4); GMAX2(v5); GMAX2(v6); GMAX2(v7);
    }
    if (j + 4 <= end) {
        int s0 = g_csr[j],     s1 = g_csr[j + 1];
        int s2 = g_csr[j + 2], s3 = g_csr[j + 3];
        uint4 v0 = *(const uint4*)(h_in + (size_t)s0 * D + dl * 8);
        uint4 v1 = *(const uint4*)(h_in + (size_t)s1 * D + dl * 8);
        uint4 v2 = *(const uint4*)(h_in + (size_t)s2 * D + dl * 8);
        uint4 v3 = *(const uint4*)(h_in + (size_t)s3 * D + dl * 8);
        GMAX2(v0); GMAX2(v1); GMAX2(v2); GMAX2(v3);
        j += 4;
    }
    if (j + 2 <= end) {
        int s0 = g_csr[j], s1 = g_csr[j + 1];
        uint4 v0 = *(const uint4*)(h_in + (size_t)s0 * D + dl * 8);
        uint4 v1 = *(const uint4*)(h_in + (size_t)s1 * D + dl * 8);
        GMAX2(v0); GMAX2(v1);
        j += 2;
    }
    if (j < end) {
        int s0 = g_csr[j];
        uint4 v0 = *(const uint4*)(h_in + (size_t)s0 * D + dl * 8);
        GMAX2(v0);
    }
    if (start == end) {
        __half2 z = __half2half2(__ushort_as_half((unsigned short)0));
        m0 = z; m1 = z; m2 = z; m3 = z;
    }
    uint4 o;
    o.x = *(unsigned*)&m0; o.y = *(unsigned*)&m1;
    o.z = *(unsigned*)&m2; o.w = *(unsigned*)&m3;
    *(uint4*)(agg_out + (size_t)node * D + dl * 8) = o;
}

// ---------------- gemm (HMMA): out = relu([agg|h] @ [Wl;Wr] + bl) ------------
template <int OUT16>
__global__ __launch_bounds__(TPB) void gemm_kernel(
    const __half* __restrict__ ag, const __half* __restrict__ hh,
    void* __restrict__ outp,
    const float* __restrict__ Wl, const float* __restrict__ bl,
    const float* __restrict__ Wr, int layer)
{
    extern __shared__ __half smem16[];
    __half* sA = smem16;                  // [128][A_PITCH]: cols 0-63 agg, 64-127 h
    __half* sW = smem16 + SA_HALVES;      // [128][W_PITCH]: rows 0-63 Wl, 64-127 Wr
    float*  sB = (float*)(smem16 + SA_HALVES + SW_HALVES);

    int tid = threadIdx.x;
    int blockBase = blockIdx.x * NPB;

    // stage W (fp32 -> fp16)
    {
        const float4* wl4 = (const float4*)(Wl + layer * D * D);
        const float4* wr4 = (const float4*)(Wr + layer * D * D);
        #pragma unroll
        for (int i = tid; i < 2048; i += TPB) {
            int row = i >> 4, c = i & 15;
            float4 v = (row < 64) ? wl4[row * 16 + c] : wr4[(row - 64) * 16 + c];
            __half2 h0 = __floats2half2_rn(v.x, v.y);
            __half2 h1 = __floats2half2_rn(v.z, v.w);
            uint2 u;
            u.x = *(unsigned*)&h0; u.y = *(unsigned*)&h1;
            *(uint2*)(sW + row * W_PITCH + c * 4) = u;
        }
        if (tid < D) sB[tid] = bl[layer * D + tid];
    }
    // stage A = [agg | h]
    #pragma unroll
    for (int i = tid; i < NPB * 8; i += TPB) {
        int row = i >> 3, c = i & 7;
        int node = blockBase + row;
        uint4 va = make_uint4(0, 0, 0, 0), vh = va;
        if (node < N_NODES) {
            va = ((const uint4*)(ag + (size_t)node * D))[c];
            vh = ((const uint4*)(hh + (size_t)node * D))[c];
        }
        *(uint4*)(sA + row * A_PITCH + c * 8)      = va;
        *(uint4*)(sA + row * A_PITCH + 64 + c * 8) = vh;
    }
    __syncthreads();

    int warp = tid >> 5, lane = tid & 31;
    float acc[8][4];
    #pragma unroll
    for (int n = 0; n < 8; n++) {
        acc[n][0] = 0.f; acc[n][1] = 0.f; acc[n][2] = 0.f; acc[n][3] = 0.f;
    }

    unsigned aBase = s2u(sA) + ((warp * 16 + (lane & 15)) * A_PITCH + (lane >> 4) * 8) * 2;
    unsigned bBase = s2u(sW) + ((lane & 15) * W_PITCH) * 2;

    #pragma unroll
    for (int kk = 0; kk < 8; kk++) {
        unsigned a0, a1, a2, a3;
        ldmx4(a0, a1, a2, a3, aBase + kk * 16 * 2);
        unsigned brow = bBase + kk * 16 * W_PITCH * 2;
        #pragma unroll
        for (int n = 0; n < 8; n++) {
            unsigned b0, b1;
            ldmx2t(b0, b1, brow + n * 8 * 2);
            mma16816(acc[n], a0, a1, a2, a3, b0, b1);
        }
    }

    // epilogue: bias + relu
    int g = lane >> 2, t = lane & 3;
    if (OUT16) {
        __syncthreads();                  // reuse sA as sC
        #pragma unroll
        for (int n = 0; n < 8; n++) {
            int col = n * 8 + t * 2;
            float bx = sB[col], by = sB[col + 1];
            __half2 h01 = __floats2half2_rn(fmaxf(acc[n][0] + bx, 0.f),
                                            fmaxf(acc[n][1] + by, 0.f));
            __half2 h23 = __floats2half2_rn(fmaxf(acc[n][2] + bx, 0.f),
                                            fmaxf(acc[n][3] + by, 0.f));
            *(__half2*)(sA + (warp * 16 + g)     * A_PITCH + col) = h01;
            *(__half2*)(sA + (warp * 16 + g + 8) * A_PITCH + col) = h23;
        }
        __syncthreads();
        __half* o16 = (__half*)outp;
        #pragma unroll
        for (int i = tid; i < NPB * 8; i += TPB) {
            int row = i >> 3, c = i & 7;
            int node = blockBase + row;
            if (node < N_NODES)
                *(uint4*)(o16 + (size_t)node * D + c * 8) =
                    *(uint4*)(sA + row * A_PITCH + c * 8);
        }
    } else {
        float* o32 = (float*)outp;
        int row0 = blockBase + warp * 16 + g;
        int row1 = row0 + 8;
        #pragma unroll
        for (int n = 0; n < 8; n++) {
            int col = n * 8 + t * 2;
            float bx = sB[col], by = sB[col + 1];
            if (row0 < N_NODES) {
                float2 v = make_float2(fmaxf(acc[n][0] + bx, 0.f),
                                       fmaxf(acc[n][1] + by, 0.f));
                *(float2*)(o32 + (size_t)row0 * D + col) = v;
            }
            if (row1 < N_NODES) {
                float2 v = make_float2(fmaxf(acc[n][2] + bx, 0.f),
                                       fmaxf(acc[n][3] + by, 0.f));
                *(float2*)(o32 + (size_t)row1 * D + col) = v;
            }
        }
    }
}

// ---------------- launch -----------------------------------------------------
extern "C" void kernel_launch(void* const* d_in, const int* in_sizes, int n_in,
                              void* d_out, int out_size) {
    const float* x  = nullptr;
    const void*  edge = nullptr;
    const float* Wl = nullptr;
    const float* Wr = nullptr;
    const float* bl = nullptr;
    for (int i = 0; i < n_in; i++) {
        int sz = in_sizes[i];
        if (sz == N_NODES * D)            x    = (const float*)d_in[i];
        else if (sz == 2 * N_EDGES)       edge = d_in[i];
        else if (sz == N_LAYERS * D * D) { if (!Wl) Wl = (const float*)d_in[i];
                                           else     Wr = (const float*)d_in[i]; }
        else if (sz == N_LAYERS * D)      bl   = (const float*)d_in[i];
    }
    float* out = (float*)d_out;

    static int smem_set = 0;
    if (!smem_set) {
        cudaFuncSetAttribute(gemm_kernel<1>,
                             cudaFuncAttributeMaxDynamicSharedMemorySize, SMEM_BYTES);
        cudaFuncSetAttribute(gemm_kernel<0>,
                             cudaFuncAttributeMaxDynamicSharedMemorySize, SMEM_BYTES);
        smem_set = 1;
    }

    init_kernel<<<1, 128>>>(edge);
    histogram_kernel<<<EBLOCKS, 256>>>(edge, x);
    scan_kernel<<<NSB, SBLK>>>();
    scatter_kernel<<<EBLOCKS, 256>>>(edge);

    int gblocks = (N_NODES + GNPB - 1) / GNPB;
    int mblocks = (N_NODES + NPB - 1) / NPB;

    __half* x16 = nullptr; __half* h16a = nullptr; __half* h16b = nullptr;
    __half* agg16 = nullptr;
    cudaGetSymbolAddress((void**)&x16, g_x16);
    cudaGetSymbolAddress((void**)&h16a, g_h16a);
    cudaGetSymbolAddress((void**)&h16b, g_h16b);
    cudaGetSymbolAddress((void**)&agg16, g_agg16);

    // layer 1
    gather16_kernel<<<gblocks, GTPB>>>(x16, agg16);
    gemm_kernel<1><<<mblocks, TPB, SMEM_BYTES>>>(agg16, x16, h16a, Wl, bl, Wr, 0);
    // layer 2
    gather16_kernel<<<gblocks, GTPB>>>(h16a, agg16);
    gemm_kernel<1><<<mblocks, TPB, SMEM_BYTES>>>(agg16, h16a, h16b, Wl, bl, Wr, 1);
    // layer 3
    gather16_kernel<<<gblocks, GTPB>>>(h16b, agg16);
    gemm_kernel<1><<<mblocks, TPB, SMEM_BYTES>>>(agg16, h16b, h16a, Wl, bl, Wr, 2);
    // layer 4: fp32 out
    gather16_kernel<<<gblocks, GTPB>>>(h16a, agg16);
    gemm_kernel<0><<<mblocks, TPB, SMEM_BYTES>>>(agg16, h16a, out, Wl, bl, Wr, 3);
}

// round 15
// speedup vs baseline: 1.0089x; 1.0089x over previous
#include <cuda_runtime.h>
#include <cuda_fp16.h>
#include <math.h>

#define N_NODES 100000
#define N_EDGES 1250000
#define D 64
#define N_LAYERS 4

// ---- gemm kernel config ----
#define TPB 256                       // 8 warps, 1 M-tile (16 nodes) each
#define NPB 128                       // nodes per block
#define A_PITCH 136                   // halves; 272B row stride -> conflict-free LDSM
#define W_PITCH 72                    // halves; 144B row stride -> conflict-free LDSM
#define SA_HALVES (NPB * A_PITCH)     // 17408
#define SW_HALVES (128 * W_PITCH)     // 9216
#define SMEM_BYTES ((SA_HALVES + SW_HALVES) * 2 + D * 4)

// ---- gather kernel config ----
#define GTPB 256
#define GNPB 32

// ---- scan config ----
#define SBLK 1024
#define NSB ((N_NODES + SBLK - 1) / SBLK)   // 98 blocks <= 148 SMs: lookback safe

// ---- edge-kernel grids ----
#define HBLOCKS ((N_EDGES / 2 + 255) / 256)   // histogram: 2 edges/thread
#define HTHREADS (HBLOCKS * 256)
#define EBLOCKS ((N_EDGES / 4 + 255) / 256)   // scatter: 4 edges/thread

// ---------------- scratch (static device globals; zero-init at load) ---------
__device__ __half g_x16[N_NODES * D];
__device__ __half g_h16a[N_NODES * D];
__device__ __half g_h16b[N_NODES * D];
__device__ __half g_agg16[N_NODES * D];
__device__ int    g_counts[N_NODES];          // invariant: all-zero at call entry
__device__ int    g_rowptr[N_NODES + 1];
__device__ int    g_cursor[N_NODES];
__device__ int    g_csr[N_EDGES];
__device__ unsigned long long g_bstat[NSB];   // lookback: flag<<32 | value
__device__ int    g_is64;

// ---------------- mma helpers ------------------------------------------------
__device__ __forceinline__ unsigned s2u(const void* p) {
    return (unsigned)__cvta_generic_to_shared(p);
}
__device__ __forceinline__ void ldmx4(unsigned& a0, unsigned& a1,
                                      unsigned& a2, unsigned& a3, unsigned addr) {
    asm volatile("ldmatrix.sync.aligned.m8n8.x4.shared.b16 {%0,%1,%2,%3}, [%4];"
                 : "=r"(a0), "=r"(a1), "=r"(a2), "=r"(a3) : "r"(addr));
}
__device__ __forceinline__ void ldmx2t(unsigned& b0, unsigned& b1, unsigned addr) {
    asm volatile("ldmatrix.sync.aligned.m8n8.x2.trans.shared.b16 {%0,%1}, [%2];"
                 : "=r"(b0), "=r"(b1) : "r"(addr));
}
__device__ __forceinline__ void mma16816(float* c, unsigned a0, unsigned a1,
                                         unsigned a2, unsigned a3,
                                         unsigned b0, unsigned b1) {
    asm volatile(
        "mma.sync.aligned.m16n8k16.row.col.f32.f16.f16.f32 "
        "{%0,%1,%2,%3}, {%4,%5,%6,%7}, {%8,%9}, {%0,%1,%2,%3};"
        : "+f"(c[0]), "+f"(c[1]), "+f"(c[2]), "+f"(c[3])
        : "r"(a0), "r"(a1), "r"(a2), "r"(a3), "r"(b0), "r"(b1));
}

// ---------------- init: dtype detect + zero lookback status (1 block) --------
__global__ void init_kernel(const void* __restrict__ edge_raw) {
    int i = threadIdx.x;
    if (i < NSB) g_bstat[i] = 0ull;
    if (i == 0) {
        const long long* e64 = (const long long*)edge_raw;
        int ok64 = 1;
        #pragma unroll 8
        for (int t = 0; t < 64; t++) {
            long long v = e64[t];
            if (v < 0 || v >= N_NODES) ok64 = 0;
        }
        g_is64 = ok64;
    }
}

// ---------------- histogram (RED, result discarded) + fused x->fp16 ----------
__global__ void histogram_kernel(const void* __restrict__ edge_raw,
                                 const float* __restrict__ x) {
    int p = blockIdx.x * blockDim.x + threadIdx.x;
    // fused conversion (grid-strided)
    #pragma unroll 1
    for (int i = p; i < N_NODES * D / 2; i += HTHREADS) {
        float2 v = ((const float2*)x)[i];
        ((__half2*)g_x16)[i] = __floats2half2_rn(v.x, v.y);
    }
    int e = p * 2;
    if (e >= N_EDGES) return;
    int d0, d1;
    if (g_is64) {
        longlong2 v = ((const longlong2*)edge_raw)[N_EDGES / 2 + p];
        d0 = (int)v.x; d1 = (int)v.y;
    } else {
        int2 v = ((const int2*)edge_raw)[N_EDGES / 2 + p];
        d0 = v.x; d1 = v.y;
    }
    if (d0 >= 0 && d0 < N_NODES) atomicAdd(&g_counts[d0], 1);   // RED (no return)
    if (e + 1 < N_EDGES && d1 >= 0 && d1 < N_NODES) atomicAdd(&g_counts[d1], 1);
}

// single-pass decoupled-lookback exclusive scan (warp-parallel lookback).
// Re-zeroes g_counts for the next call (module load guarantees first-call zero).
__global__ __launch_bounds__(SBLK) void scan_kernel() {
    __shared__ int wsum[32];
    __shared__ int sPrefix;
    int tid = threadIdx.x, lane = tid & 31, w = tid >> 5;
    int bid = blockIdx.x;
    int i = bid * SBLK + tid;
    int v = (i < N_NODES) ? g_counts[i] : 0;
    if (i < N_NODES) g_counts[i] = 0;         // restore invariant for next call

    int x = v;
    #pragma unroll
    for (int off = 1; off < 32; off <<= 1) {
        int y = __shfl_up_sync(0xffffffffu, x, off);
        if (lane >= off) x += y;
    }
    if (lane == 31) wsum[w] = x;
    __syncthreads();
    if (w == 0) {
        int s = wsum[lane];
        #pragma unroll
        for (int off = 1; off < 32; off <<= 1) {
            int y = __shfl_up_sync(0xffffffffu, s, off);
            if (lane >= off) s += y;
        }
        wsum[lane] = s;
    }
    __syncthreads();
    int incl = x + ((w > 0) ? wsum[w - 1] : 0);
    int total = wsum[31];                     // block aggregate

    if (w == 0) {                             // warp 0: publish + lookback
        int prefix = 0;
        if (bid > 0) {
            if (lane == 0)
                atomicExch(&g_bstat[bid], (1ull << 32) | (unsigned)total);
            int p = bid - 1;
            while (true) {
                int idx = p - lane;           // lane 0 = nearest predecessor
                unsigned long long s = (idx >= 0)
                    ? atomicAdd(&g_bstat[idx], 0ull) : (2ull << 32);
                unsigned flag = (unsigned)(s >> 32);
                if (!__all_sync(0xffffffffu, flag != 0u)) continue;  // retry window
                unsigned stopmask = __ballot_sync(0xffffffffu, flag == 2u);
                int firstStop = stopmask ? (__ffs(stopmask) - 1) : 32;
                int val = (idx >= 0 && lane <= firstStop) ? (int)(unsigned)s : 0;
                #pragma unroll
                for (int o = 16; o; o >>= 1)
                    val += __shfl_xor_sync(0xffffffffu, val, o);
                prefix += val;
                if (stopmask) break;
                p -= 32;
            }
        }
        if (lane == 0) {
            sPrefix = prefix;
            atomicExch(&g_bstat[bid], (2ull << 32) | (unsigned)(prefix + total));
        }
    }
    __syncthreads();
    int base = sPrefix;
    if (i < N_NODES) {
        int r = base + incl - v;
        g_rowptr[i] = r;
        g_cursor[i] = r;
    }
    if (bid == NSB - 1 && tid == 0) g_rowptr[N_NODES] = base + total;
}

// scatter: 4 edges/thread, cursor atomics (the one returning-atomic pass)
__global__ void scatter_kernel(const void* __restrict__ edge_raw) {
    int p = blockIdx.x * blockDim.x + threadIdx.x;
    int e = p * 4;
    if (e >= N_EDGES) return;
    int s0, s1, s2, s3, d0, d1, d2, d3;
    int is64 = g_is64;
    if (is64) {
        longlong2 v0 = ((const longlong2*)edge_raw)[2 * p];
        longlong2 v1 = ((const longlong2*)edge_raw)[2 * p + 1];
        s0 = (int)v0.x; s1 = (int)v0.y; s2 = (int)v1.x; s3 = (int)v1.y;
        longlong2 w0 = ((const longlong2*)edge_raw)[N_EDGES / 2 + 2 * p];
        longlong2 w1 = ((const longlong2*)edge_raw)[N_EDGES / 2 + 2 * p + 1];
        d0 = (int)w0.x; d1 = (int)w0.y; d2 = (int)w1.x; d3 = (int)w1.y;
    } else {
        int4 sv = ((const int4*)edge_raw)[p];
        int4 dv = ((const int4*)edge_raw)[N_EDGES / 4 + p];
        s0 = sv.x; s1 = sv.y; s2 = sv.z; s3 = sv.w;
        d0 = dv.x; d1 = dv.y; d2 = dv.z; d3 = dv.w;
    }
    if (s0 >= 0 && s0 < N_NODES && d0 >= 0 && d0 < N_NODES) {
        int pos = atomicAdd(&g_cursor[d0], 1);
        if (pos >= 0 && pos < N_EDGES) g_csr[pos] = s0;
    }
    if (s1 >= 0 && s1 < N_NODES && d1 >= 0 && d1 < N_NODES) {
        int pos = atomicAdd(&g_cursor[d1], 1);
        if (pos >= 0 && pos < N_EDGES) g_csr[pos] = s1;
    }
    if (s2 >= 0 && s2 < N_NODES && d2 >= 0 && d2 < N_NODES) {
        int pos = atomicAdd(&g_cursor[d2], 1);
        if (pos >= 0 && pos < N_EDGES) g_csr[pos] = s2;
    }
    if (s3 >= 0 && s3 < N_NODES && d3 >= 0 && d3 < N_NODES) {
        int pos = atomicAdd(&g_cursor[d3], 1);
        if (pos >= 0 && pos < N_EDGES) g_csr[pos] = s3;
    }
}

// ---------------- gather fp16: h16 -> agg16 ----------------------------------
#define GMAX2(v) do { \
    m0 = __hmax2(m0, *(__half2*)&(v).x); m1 = __hmax2(m1, *(__half2*)&(v).y); \
    m2 = __hmax2(m2, *(__half2*)&(v).z); m3 = __hmax2(m3, *(__half2*)&(v).w); } while (0)

__global__ __launch_bounds__(GTPB) void gather16_kernel(
    const __half* __restrict__ h_in, __half* __restrict__ agg_out)
{
    int tid = threadIdx.x;
    int warp = tid >> 5, lane = tid & 31;
    int sub = lane >> 3, dl = lane & 7;

    int node = blockIdx.x * GNPB + warp * 4 + sub;
    if (node >= N_NODES) return;
    int start = g_rowptr[node];
    int end   = g_rowptr[node + 1];

    const __half neginf = __ushort_as_half((unsigned short)0xFC00);
    __half2 m0 = __half2half2(neginf), m1 = m0, m2 = m0, m3 = m0;

    int j = start;
    #pragma unroll 1
    for (; j + 8 <= end; j += 8) {
        int s0 = g_csr[j],     s1 = g_csr[j + 1];
        int s2 = g_csr[j + 2], s3 = g_csr[j + 3];
        int s4 = g_csr[j + 4], s5 = g_csr[j + 5];
        int s6 = g_csr[j + 6], s7 = g_csr[j + 7];
        uint4 v0 = *(const uint4*)(h_in + (size_t)s0 * D + dl * 8);
        uint4 v1 = *(const uint4*)(h_in + (size_t)s1 * D + dl * 8);
        uint4 v2 = *(const uint4*)(h_in + (size_t)s2 * D + dl * 8);
        uint4 v3 = *(const uint4*)(h_in + (size_t)s3 * D + dl * 8);
        uint4 v4 = *(const uint4*)(h_in + (size_t)s4 * D + dl * 8);
        uint4 v5 = *(const uint4*)(h_in + (size_t)s5 * D + dl * 8);
        uint4 v6 = *(const uint4*)(h_in + (size_t)s6 * D + dl * 8);
        uint4 v7 = *(const uint4*)(h_in + (size_t)s7 * D + dl * 8);
        GMAX2(v0); GMAX2(v1); GMAX2(v2); GMAX2(v3);
        GMAX2(v4); GMAX2(v5); GMAX2(v6); GMAX2(v7);
    }
    if (j + 4 <= end) {
        int s0 = g_csr[j],     s1 = g_csr[j + 1];
        int s2 = g_csr[j + 2], s3 = g_csr[j + 3];
        uint4 v0 = *(const uint4*)(h_in + (size_t)s0 * D + dl * 8);
        uint4 v1 = *(const uint4*)(h_in + (size_t)s1 * D + dl * 8);
        uint4 v2 = *(const uint4*)(h_in + (size_t)s2 * D + dl * 8);
        uint4 v3 = *(const uint4*)(h_in + (size_t)s3 * D + dl * 8);
        GMAX2(v0); GMAX2(v1); GMAX2(v2); GMAX2(v3);
        j += 4;
    }
    if (j + 2 <= end) {
        int s0 = g_csr[j], s1 = g_csr[j + 1];
        uint4 v0 = *(const uint4*)(h_in + (size_t)s0 * D + dl * 8);
        uint4 v1 = *(const uint4*)(h_in + (size_t)s1 * D + dl * 8);
        GMAX2(v0); GMAX2(v1);
        j += 2;
    }
    if (j < end) {
        int s0 = g_csr[j];
        uint4 v0 = *(const uint4*)(h_in + (size_t)s0 * D + dl * 8);
        GMAX2(v0);
    }
    if (start == end) {
        __half2 z = __half2half2(__ushort_as_half((unsigned short)0));
        m0 = z; m1 = z; m2 = z; m3 = z;
    }
    uint4 o;
    o.x = *(unsigned*)&m0; o.y = *(unsigned*)&m1;
    o.z = *(unsigned*)&m2; o.w = *(unsigned*)&m3;
    *(uint4*)(agg_out + (size_t)node * D + dl * 8) = o;
}

// ---------------- gemm (HMMA): out = relu([agg|h] @ [Wl;Wr] + bl) ------------
template <int OUT16>
__global__ __launch_bounds__(TPB) void gemm_kernel(
    const __half* __restrict__ ag, const __half* __restrict__ hh,
    void* __restrict__ outp,
    const float* __restrict__ Wl, const float* __restrict__ bl,
    const float* __restrict__ Wr, int layer)
{
    extern __shared__ __half smem16[];
    __half* sA = smem16;                  // [128][A_PITCH]: cols 0-63 agg, 64-127 h
    __half* sW = smem16 + SA_HALVES;      // [128][W_PITCH]: rows 0-63 Wl, 64-127 Wr
    float*  sB = (float*)(smem16 + SA_HALVES + SW_HALVES);

    int tid = threadIdx.x;
    int blockBase = blockIdx.x * NPB;

    // stage W (fp32 -> fp16)
    {
        const float4* wl4 = (const float4*)(Wl + layer * D * D);
        const float4* wr4 = (const float4*)(Wr + layer * D * D);
        #pragma unroll
        for (int i = tid; i < 2048; i += TPB) {
            int row = i >> 4, c = i & 15;
            float4 v = (row < 64) ? wl4[row * 16 + c] : wr4[(row - 64) * 16 + c];
            __half2 h0 = __floats2half2_rn(v.x, v.y);
            __half2 h1 = __floats2half2_rn(v.z, v.w);
            uint2 u;
            u.x = *(unsigned*)&h0; u.y = *(unsigned*)&h1;
            *(uint2*)(sW + row * W_PITCH + c * 4) = u;
        }
        if (tid < D) sB[tid] = bl[layer * D + tid];
    }
    // stage A = [agg | h]
    #pragma unroll
    for (int i = tid; i < NPB * 8; i += TPB) {
        int row = i >> 3, c = i & 7;
        int node = blockBase + row;
        uint4 va = make_uint4(0, 0, 0, 0), vh = va;
        if (node < N_NODES) {
            va = ((const uint4*)(ag + (size_t)node * D))[c];
            vh = ((const uint4*)(hh + (size_t)node * D))[c];
        }
        *(uint4*)(sA + row * A_PITCH + c * 8)      = va;
        *(uint4*)(sA + row * A_PITCH + 64 + c * 8) = vh;
    }
    __syncthreads();

    int warp = tid >> 5, lane = tid & 31;
    float acc[8][4];
    #pragma unroll
    for (int n = 0; n < 8; n++) {
        acc[n][0] = 0.f; acc[n][1] = 0.f; acc[n][2] = 0.f; acc[n][3] = 0.f;
    }

    unsigned aBase = s2u(sA) + ((warp * 16 + (lane & 15)) * A_PITCH + (lane >> 4) * 8) * 2;
    unsigned bBase = s2u(sW) + ((lane & 15) * W_PITCH) * 2;

    #pragma unroll
    for (int kk = 0; kk < 8; kk++) {
        unsigned a0, a1, a2, a3;
        ldmx4(a0, a1, a2, a3, aBase + kk * 16 * 2);
        unsigned brow = bBase + kk * 16 * W_PITCH * 2;
        #pragma unroll
        for (int n = 0; n < 8; n++) {
            unsigned b0, b1;
            ldmx2t(b0, b1, brow + n * 8 * 2);
            mma16816(acc[n], a0, a1, a2, a3, b0, b1);
        }
    }

    // epilogue: bias + relu
    int g = lane >> 2, t = lane & 3;
    if (OUT16) {
        __syncthreads();                  // reuse sA as sC
        #pragma unroll
        for (int n = 0; n < 8; n++) {
            int col = n * 8 + t * 2;
            float bx = sB[col], by = sB[col + 1];
            __half2 h01 = __floats2half2_rn(fmaxf(acc[n][0] + bx, 0.f),
                                            fmaxf(acc[n][1] + by, 0.f));
            __half2 h23 = __floats2half2_rn(fmaxf(acc[n][2] + bx, 0.f),
                                            fmaxf(acc[n][3] + by, 0.f));
            *(__half2*)(sA + (warp * 16 + g)     * A_PITCH + col) = h01;
            *(__half2*)(sA + (warp * 16 + g + 8) * A_PITCH + col) = h23;
        }
        __syncthreads();
        __half* o16 = (__half*)outp;
        #pragma unroll
        for (int i = tid; i < NPB * 8; i += TPB) {
            int row = i >> 3, c = i & 7;
            int node = blockBase + row;
            if (node < N_NODES)
                *(uint4*)(o16 + (size_t)node * D + c * 8) =
                    *(uint4*)(sA + row * A_PITCH + c * 8);
        }
    } else {
        float* o32 = (float*)outp;
        int row0 = blockBase + warp * 16 + g;
        int row1 = row0 + 8;
        #pragma unroll
        for (int n = 0; n < 8; n++) {
            int col = n * 8 + t * 2;
            float bx = sB[col], by = sB[col + 1];
            if (row0 < N_NODES) {
                float2 v = make_float2(fmaxf(acc[n][0] + bx, 0.f),
                                       fmaxf(acc[n][1] + by, 0.f));
                *(float2*)(o32 + (size_t)row0 * D + col) = v;
            }
            if (row1 < N_NODES) {
                float2 v = make_float2(fmaxf(acc[n][2] + bx, 0.f),
                                       fmaxf(acc[n][3] + by, 0.f));
                *(float2*)(o32 + (size_t)row1 * D + col) = v;
            }
        }
    }
}

// ---------------- launch -----------------------------------------------------
extern "C" void kernel_launch(void* const* d_in, const int* in_sizes, int n_in,
                              void* d_out, int out_size) {
    const float* x  = nullptr;
    const void*  edge = nullptr;
    const float* Wl = nullptr;
    const float* Wr = nullptr;
    const float* bl = nullptr;
    for (int i = 0; i < n_in; i++) {
        int sz = in_sizes[i];
        if (sz == N_NODES * D)            x    = (const float*)d_in[i];
        else if (sz == 2 * N_EDGES)       edge = d_in[i];
        else if (sz == N_LAYERS * D * D) { if (!Wl) Wl = (const float*)d_in[i];
                                           else     Wr = (const float*)d_in[i]; }
        else if (sz == N_LAYERS * D)      bl   = (const float*)d_in[i];
    }
    float* out = (float*)d_out;

    static int smem_set = 0;
    if (!smem_set) {
        cudaFuncSetAttribute(gemm_kernel<1>,
                             cudaFuncAttributeMaxDynamicSharedMemorySize, SMEM_BYTES);
        cudaFuncSetAttribute(gemm_kernel<0>,
                             cudaFuncAttributeMaxDynamicSharedMemorySize, SMEM_BYTES);
        smem_set = 1;
    }

    init_kernel<<<1, 128>>>(edge);
    histogram_kernel<<<HBLOCKS, 256>>>(edge, x);
    scan_kernel<<<NSB, SBLK>>>();
    scatter_kernel<<<EBLOCKS, 256>>>(edge);

    int gblocks = (N_NODES + GNPB - 1) / GNPB;
    int mblocks = (N_NODES + NPB - 1) / NPB;

    __half* x16 = nullptr; __half* h16a = nullptr; __half* h16b = nullptr;
    __half* agg16 = nullptr;
    cudaGetSymbolAddress((void**)&x16, g_x16);
    cudaGetSymbolAddress((void**)&h16a, g_h16a);
    cudaGetSymbolAddress((void**)&h16b, g_h16b);
    cudaGetSymbolAddress((void**)&agg16, g_agg16);

    // layer 1
    gather16_kernel<<<gblocks, GTPB>>>(x16, agg16);
    gemm_kernel<1><<<mblocks, TPB, SMEM_BYTES>>>(agg16, x16, h16a, Wl, bl, Wr, 0);
    // layer 2
    gather16_kernel<<<gblocks, GTPB>>>(h16a, agg16);
    gemm_kernel<1><<<mblocks, TPB, SMEM_BYTES>>>(agg16, h16a, h16b, Wl, bl, Wr, 1);
    // layer 3
    gather16_kernel<<<gblocks, GTPB>>>(h16b, agg16);
    gemm_kernel<1><<<mblocks, TPB, SMEM_BYTES>>>(agg16, h16b, h16a, Wl, bl, Wr, 2);
    // layer 4: fp32 out
    gather16_kernel<<<gblocks, GTPB>>>(h16a, agg16);
    gemm_kernel<0><<<mblocks, TPB, SMEM_BYTES>>>(agg16, h16a, out, Wl, bl, Wr, 3);
}

// round 16
// speedup vs baseline: 1.0249x; 1.0158x over previous
#include <cuda_runtime.h>
#include <cuda_fp16.h>
#include <math.h>

#define N_NODES 100000
#define N_EDGES 1250000
#define D 64
#define N_LAYERS 4

// ---- gemm kernel config ----
#define TPB 256                       // 8 warps, 1 M-tile (16 nodes) each
#define NPB 128                       // nodes per block
#define A_PITCH 136                   // halves; 272B row stride -> conflict-free LDSM
#define W_PITCH 72                    // halves; 144B row stride -> conflict-free LDSM
#define SA_HALVES (NPB * A_PITCH)     // 17408
#define SW_HALVES (128 * W_PITCH)     // 9216
#define SMEM_BYTES ((SA_HALVES + SW_HALVES) * 2 + D * 4)

// ---- gather kernel config ----
#define GTPB 256
#define GNPB 32

// ---- scan config ----
#define SBLK 1024
#define NSB ((N_NODES + SBLK - 1) / SBLK)   // 98 blocks <= 148 SMs: lookback safe

// ---- edge-kernel grid (2 edges per thread) ----
#define HBLOCKS ((N_EDGES / 2 + 255) / 256)
#define HTHREADS (HBLOCKS * 256)

// ---------------- scratch (static device globals; zero-init at load) ---------
__device__ __half g_x16[N_NODES * D];
__device__ __half g_h16a[N_NODES * D];
__device__ __half g_h16b[N_NODES * D];
__device__ __half g_agg16[N_NODES * D];
__device__ __half g_w16[N_LAYERS * 128 * D];  // per layer: rows 0-63 Wl, 64-127 Wr
__device__ int    g_counts[N_NODES];          // invariant: all-zero at call entry
__device__ int    g_rowptr[N_NODES + 1];
__device__ int    g_cursor[N_NODES];
__device__ int    g_csr[N_EDGES];
__device__ unsigned long long g_bstat[NSB];   // lookback: flag<<32 | value
__device__ int    g_is64;

// ---------------- mma helpers ------------------------------------------------
__device__ __forceinline__ unsigned s2u(const void* p) {
    return (unsigned)__cvta_generic_to_shared(p);
}
__device__ __forceinline__ void ldmx4(unsigned& a0, unsigned& a1,
                                      unsigned& a2, unsigned& a3, unsigned addr) {
    asm volatile("ldmatrix.sync.aligned.m8n8.x4.shared.b16 {%0,%1,%2,%3}, [%4];"
                 : "=r"(a0), "=r"(a1), "=r"(a2), "=r"(a3) : "r"(addr));
}
__device__ __forceinline__ void ldmx2t(unsigned& b0, unsigned& b1, unsigned addr) {
    asm volatile("ldmatrix.sync.aligned.m8n8.x2.trans.shared.b16 {%0,%1}, [%2];"
                 : "=r"(b0), "=r"(b1) : "r"(addr));
}
__device__ __forceinline__ void mma16816(float* c, unsigned a0, unsigned a1,
                                         unsigned a2, unsigned a3,
                                         unsigned b0, unsigned b1) {
    asm volatile(
        "mma.sync.aligned.m16n8k16.row.col.f32.f16.f16.f32 "
        "{%0,%1,%2,%3}, {%4,%5,%6,%7}, {%8,%9}, {%0,%1,%2,%3};"
        : "+f"(c[0]), "+f"(c[1]), "+f"(c[2]), "+f"(c[3])
        : "r"(a0), "r"(a1), "r"(a2), "r"(a3), "r"(b0), "r"(b1));
}

// ---------------- init: dtype detect + zero status + W -> fp16 ----------------
// Grid: 64 blocks x 256. Converts Wl/Wr (32768 floats = 16384 half2).
__global__ void init_kernel(const void* __restrict__ edge_raw,
                            const float* __restrict__ Wl,
                            const float* __restrict__ Wr) {
    int i = blockIdx.x * blockDim.x + threadIdx.x;
    if (i < 16384) {
        int mat = i >> 13;                 // 0 = Wl, 1 = Wr
        int r = i & 8191;                  // half2 index within matrix set
        int l = r >> 11;                   // layer
        int rem = r & 2047;
        int row = rem >> 5;                // 0..63
        int cp = rem & 31;                 // column pair
        const float2* src = (const float2*)(mat ? Wr : Wl);
        float2 v = src[r];
        __half2 h = __floats2half2_rn(v.x, v.y);
        int drow = row + (mat ? 64 : 0);
        *(__half2*)(g_w16 + l * (128 * D) + drow * D + cp * 2) = h;
    }
    if (i < NSB) g_bstat[i] = 0ull;
    if (i == 0) {
        const long long* e64 = (const long long*)edge_raw;
        int ok64 = 1;
        #pragma unroll 8
        for (int t = 0; t < 64; t++) {
            long long v = e64[t];
            if (v < 0 || v >= N_NODES) ok64 = 0;
        }
        g_is64 = ok64;
    }
}

// ---------------- histogram (RED, result discarded) + fused x->fp16 ----------
__global__ void histogram_kernel(const void* __restrict__ edge_raw,
                                 const float* __restrict__ x) {
    int p = blockIdx.x * blockDim.x + threadIdx.x;
    // fused conversion (grid-strided)
    #pragma unroll 1
    for (int i = p; i < N_NODES * D / 2; i += HTHREADS) {
        float2 v = ((const float2*)x)[i];
        ((__half2*)g_x16)[i] = __floats2half2_rn(v.x, v.y);
    }
    int e = p * 2;
    if (e >= N_EDGES) return;
    int d0, d1;
    if (g_is64) {
        longlong2 v = ((const longlong2*)edge_raw)[N_EDGES / 2 + p];
        d0 = (int)v.x; d1 = (int)v.y;
    } else {
        int2 v = ((const int2*)edge_raw)[N_EDGES / 2 + p];
        d0 = v.x; d1 = v.y;
    }
    if (d0 >= 0 && d0 < N_NODES) atomicAdd(&g_counts[d0], 1);   // RED (no return)
    if (e + 1 < N_EDGES && d1 >= 0 && d1 < N_NODES) atomicAdd(&g_counts[d1], 1);
}

// single-pass decoupled-lookback exclusive scan (warp-parallel lookback).
// Re-zeroes g_counts for the next call (module load guarantees first-call zero).
__global__ __launch_bounds__(SBLK) void scan_kernel() {
    __shared__ int wsum[32];
    __shared__ int sPrefix;
    int tid = threadIdx.x, lane = tid & 31, w = tid >> 5;
    int bid = blockIdx.x;
    int i = bid * SBLK + tid;
    int v = (i < N_NODES) ? g_counts[i] : 0;
    if (i < N_NODES) g_counts[i] = 0;         // restore invariant for next call

    int x = v;
    #pragma unroll
    for (int off = 1; off < 32; off <<= 1) {
        int y = __shfl_up_sync(0xffffffffu, x, off);
        if (lane >= off) x += y;
    }
    if (lane == 31) wsum[w] = x;
    __syncthreads();
    if (w == 0) {
        int s = wsum[lane];
        #pragma unroll
        for (int off = 1; off < 32; off <<= 1) {
            int y = __shfl_up_sync(0xffffffffu, s, off);
            if (lane >= off) s += y;
        }
        wsum[lane] = s;
    }
    __syncthreads();
    int incl = x + ((w > 0) ? wsum[w - 1] : 0);
    int total = wsum[31];                     // block aggregate

    if (w == 0) {                             // warp 0: publish + lookback
        int prefix = 0;
        if (bid > 0) {
            if (lane == 0)
                atomicExch(&g_bstat[bid], (1ull << 32) | (unsigned)total);
            int p = bid - 1;
            while (true) {
                int idx = p - lane;           // lane 0 = nearest predecessor
                unsigned long long s = (idx >= 0)
                    ? atomicAdd(&g_bstat[idx], 0ull) : (2ull << 32);
                unsigned flag = (unsigned)(s >> 32);
                if (!__all_sync(0xffffffffu, flag != 0u)) continue;  // retry window
                unsigned stopmask = __ballot_sync(0xffffffffu, flag == 2u);
                int firstStop = stopmask ? (__ffs(stopmask) - 1) : 32;
                int val = (idx >= 0 && lane <= firstStop) ? (int)(unsigned)s : 0;
                #pragma unroll
                for (int o = 16; o; o >>= 1)
                    val += __shfl_xor_sync(0xffffffffu, val, o);
                prefix += val;
                if (stopmask) break;
                p -= 32;
            }
        }
        if (lane == 0) {
            sPrefix = prefix;
            atomicExch(&g_bstat[bid], (2ull << 32) | (unsigned)(prefix + total));
        }
    }
    __syncthreads();
    int base = sPrefix;
    if (i < N_NODES) {
        int r = base + incl - v;
        g_rowptr[i] = r;
        g_cursor[i] = r;
    }
    if (bid == NSB - 1 && tid == 0) g_rowptr[N_NODES] = base + total;
}

// scatter: 2 edges/thread, cursor atomics (the one returning-atomic pass)
__global__ void scatter_kernel(const void* __restrict__ edge_raw) {
    int p = blockIdx.x * blockDim.x + threadIdx.x;      // edge pair index
    int e = p * 2;
    if (e >= N_EDGES) return;
    int s0, s1, d0, d1;
    int is64 = g_is64;
    if (is64) {
        longlong2 sv = ((const longlong2*)edge_raw)[p];
        longlong2 dv = ((const longlong2*)edge_raw)[N_EDGES / 2 + p];
        s0 = (int)sv.x; s1 = (int)sv.y; d0 = (int)dv.x; d1 = (int)dv.y;
    } else {
        int2 sv = ((const int2*)edge_raw)[p];
        int2 dv = ((const int2*)edge_raw)[N_EDGES / 2 + p];
        s0 = sv.x; s1 = sv.y; d0 = dv.x; d1 = dv.y;
    }
    if (s0 >= 0 && s0 < N_NODES && d0 >= 0 && d0 < N_NODES) {
        int pos = atomicAdd(&g_cursor[d0], 1);
        if (pos >= 0 && pos < N_EDGES) g_csr[pos] = s0;
    }
    if (e + 1 < N_EDGES && s1 >= 0 && s1 < N_NODES && d1 >= 0 && d1 < N_NODES) {
        int pos = atomicAdd(&g_cursor[d1], 1);
        if (pos >= 0 && pos < N_EDGES) g_csr[pos] = s1;
    }
}

// ---------------- gather fp16: h16 -> agg16 ----------------------------------
#define GMAX2(v) do { \
    m0 = __hmax2(m0, *(__half2*)&(v).x); m1 = __hmax2(m1, *(__half2*)&(v).y); \
    m2 = __hmax2(m2, *(__half2*)&(v).z); m3 = __hmax2(m3, *(__half2*)&(v).w); } while (0)

__global__ __launch_bounds__(GTPB) void gather16_kernel(
    const __half* __restrict__ h_in, __half* __restrict__ agg_out)
{
    int tid = threadIdx.x;
    int warp = tid >> 5, lane = tid & 31;
    int sub = lane >> 3, dl = lane & 7;

    int node = blockIdx.x * GNPB + warp * 4 + sub;
    if (node >= N_NODES) return;
    int start = g_rowptr[node];
    int end   = g_rowptr[node + 1];

    const __half neginf = __ushort_as_half((unsigned short)0xFC00);
    __half2 m0 = __half2half2(neginf), m1 = m0, m2 = m0, m3 = m0;

    int j = start;
    #pragma unroll 1
    for (; j + 8 <= end; j += 8) {
        int s0 = g_csr[j],     s1 = g_csr[j + 1];
        int s2 = g_csr[j + 2], s3 = g_csr[j + 3];
        int s4 = g_csr[j + 4], s5 = g_csr[j + 5];
        int s6 = g_csr[j + 6], s7 = g_csr[j + 7];
        uint4 v0 = *(const uint4*)(h_in + (size_t)s0 * D + dl * 8);
        uint4 v1 = *(const uint4*)(h_in + (size_t)s1 * D + dl * 8);
        uint4 v2 = *(const uint4*)(h_in + (size_t)s2 * D + dl * 8);
        uint4 v3 = *(const uint4*)(h_in + (size_t)s3 * D + dl * 8);
        uint4 v4 = *(const uint4*)(h_in + (size_t)s4 * D + dl * 8);
        uint4 v5 = *(const uint4*)(h_in + (size_t)s5 * D + dl * 8);
        uint4 v6 = *(const uint4*)(h_in + (size_t)s6 * D + dl * 8);
        uint4 v7 = *(const uint4*)(h_in + (size_t)s7 * D + dl * 8);
        GMAX2(v0); GMAX2(v1); GMAX2(v2); GMAX2(v3);
        GMAX2(v4); GMAX2(v5); GMAX2(v6); GMAX2(v7);
    }
    if (j + 4 <= end) {
        int s0 = g_csr[j],     s1 = g_csr[j + 1];
        int s2 = g_csr[j + 2], s3 = g_csr[j + 3];
        uint4 v0 = *(const uint4*)(h_in + (size_t)s0 * D + dl * 8);
        uint4 v1 = *(const uint4*)(h_in + (size_t)s1 * D + dl * 8);
        uint4 v2 = *(const uint4*)(h_in + (size_t)s2 * D + dl * 8);
        uint4 v3 = *(const uint4*)(h_in + (size_t)s3 * D + dl * 8);
        GMAX2(v0); GMAX2(v1); GMAX2(v2); GMAX2(v3);
        j += 4;
    }
    if (j + 2 <= end) {
        int s0 = g_csr[j], s1 = g_csr[j + 1];
        uint4 v0 = *(const uint4*)(h_in + (size_t)s0 * D + dl * 8);
        uint4 v1 = *(const uint4*)(h_in + (size_t)s1 * D + dl * 8);
        GMAX2(v0); GMAX2(v1);
        j += 2;
    }
    if (j < end) {
        int s0 = g_csr[j];
        uint4 v0 = *(const uint4*)(h_in + (size_t)s0 * D + dl * 8);
        GMAX2(v0);
    }
    if (start == end) {
        __half2 z = __half2half2(__ushort_as_half((unsigned short)0));
        m0 = z; m1 = z; m2 = z; m3 = z;
    }
    uint4 o;
    o.x = *(unsigned*)&m0; o.y = *(unsigned*)&m1;
    o.z = *(unsigned*)&m2; o.w = *(unsigned*)&m3;
    *(uint4*)(agg_out + (size_t)node * D + dl * 8) = o;
}

// ---------------- gemm (HMMA): out = relu([agg|h] @ [Wl;Wr] + bl) ------------
template <int OUT16>
__global__ __launch_bounds__(TPB) void gemm_kernel(
    const __half* __restrict__ ag, const __half* __restrict__ hh,
    void* __restrict__ outp,
    const float* __restrict__ bl, int layer)
{
    extern __shared__ __half smem16[];
    __half* sA = smem16;                  // [128][A_PITCH]: cols 0-63 agg, 64-127 h
    __half* sW = smem16 + SA_HALVES;      // [128][W_PITCH]: rows 0-63 Wl, 64-127 Wr
    float*  sB = (float*)(smem16 + SA_HALVES + SW_HALVES);

    int tid = threadIdx.x;
    int blockBase = blockIdx.x * NPB;

    // stage W (pre-converted fp16, coalesced uint4)
    {
        const uint4* w16 = (const uint4*)(g_w16 + layer * (128 * D));
        #pragma unroll
        for (int i = tid; i < 1024; i += TPB) {     // 128 rows x 8 uint4
            int row = i >> 3, c = i & 7;
            *(uint4*)(sW + row * W_PITCH + c * 8) = w16[i];
        }
        if (tid < D) sB[tid] = bl[layer * D + tid];
    }
    // stage A = [agg | h]
    #pragma unroll
    for (int i = tid; i < NPB * 8; i += TPB) {
        int row = i >> 3, c = i & 7;
        int node = blockBase + row;
        uint4 va = make_uint4(0, 0, 0, 0), vh = va;
        if (node < N_NODES) {
            va = ((const uint4*)(ag + (size_t)node * D))[c];
            vh = ((const uint4*)(hh + (size_t)node * D))[c];
        }
        *(uint4*)(sA + row * A_PITCH + c * 8)      = va;
        *(uint4*)(sA + row * A_PITCH + 64 + c * 8) = vh;
    }
    __syncthreads();

    int warp = tid >> 5, lane = tid & 31;
    float acc[8][4];
    #pragma unroll
    for (int n = 0; n < 8; n++) {
        acc[n][0] = 0.f; acc[n][1] = 0.f; acc[n][2] = 0.f; acc[n][3] = 0.f;
    }

    unsigned aBase = s2u(sA) + ((warp * 16 + (lane & 15)) * A_PITCH + (lane >> 4) * 8) * 2;
    unsigned bBase = s2u(sW) + ((lane & 15) * W_PITCH) * 2;

    #pragma unroll
    for (int kk = 0; kk < 8; kk++) {
        unsigned a0, a1, a2, a3;
        ldmx4(a0, a1, a2, a3, aBase + kk * 16 * 2);
        unsigned brow = bBase + kk * 16 * W_PITCH * 2;
        #pragma unroll
        for (int n = 0; n < 8; n++) {
            unsigned b0, b1;
            ldmx2t(b0, b1, brow + n * 8 * 2);
            mma16816(acc[n], a0, a1, a2, a3, b0, b1);
        }
    }

    // epilogue: bias + relu
    int g = lane >> 2, t = lane & 3;
    if (OUT16) {
        __syncthreads();                  // reuse sA as sC
        #pragma unroll
        for (int n = 0; n < 8; n++) {
            int col = n * 8 + t * 2;
            float bx = sB[col], by = sB[col + 1];
            __half2 h01 = __floats2half2_rn(fmaxf(acc[n][0] + bx, 0.f),
                                            fmaxf(acc[n][1] + by, 0.f));
            __half2 h23 = __floats2half2_rn(fmaxf(acc[n][2] + bx, 0.f),
                                            fmaxf(acc[n][3] + by, 0.f));
            *(__half2*)(sA + (warp * 16 + g)     * A_PITCH + col) = h01;
            *(__half2*)(sA + (warp * 16 + g + 8) * A_PITCH + col) = h23;
        }
        __syncthreads();
        __half* o16 = (__half*)outp;
        #pragma unroll
        for (int i = tid; i < NPB * 8; i += TPB) {
            int row = i >> 3, c = i & 7;
            int node = blockBase + row;
            if (node < N_NODES)
                *(uint4*)(o16 + (size_t)node * D + c * 8) =
                    *(uint4*)(sA + row * A_PITCH + c * 8);
        }
    } else {
        float* o32 = (float*)outp;
        int row0 = blockBase + warp * 16 + g;
        int row1 = row0 + 8;
        #pragma unroll
        for (int n = 0; n < 8; n++) {
            int col = n * 8 + t * 2;
            float bx = sB[col], by = sB[col + 1];
            if (row0 < N_NODES) {
                float2 v = make_float2(fmaxf(acc[n][0] + bx, 0.f),
                                       fmaxf(acc[n][1] + by, 0.f));
                *(float2*)(o32 + (size_t)row0 * D + col) = v;
            }
            if (row1 < N_NODES) {
                float2 v = make_float2(fmaxf(acc[n][2] + bx, 0.f),
                                       fmaxf(acc[n][3] + by, 0.f));
                *(float2*)(o32 + (size_t)row1 * D + col) = v;
            }
        }
    }
}

// ---------------- launch -----------------------------------------------------
extern "C" void kernel_launch(void* const* d_in, const int* in_sizes, int n_in,
                              void* d_out, int out_size) {
    const float* x  = nullptr;
    const void*  edge = nullptr;
    const float* Wl = nullptr;
    const float* Wr = nullptr;
    const float* bl = nullptr;
    for (int i = 0; i < n_in; i++) {
        int sz = in_sizes[i];
        if (sz == N_NODES * D)            x    = (const float*)d_in[i];
        else if (sz == 2 * N_EDGES)       edge = d_in[i];
        else if (sz == N_LAYERS * D * D) { if (!Wl) Wl = (const float*)d_in[i];
                                           else     Wr = (const float*)d_in[i]; }
        else if (sz == N_LAYERS * D)      bl   = (const float*)d_in[i];
    }
    float* out = (float*)d_out;

    static int smem_set = 0;
    if (!smem_set) {
        cudaFuncSetAttribute(gemm_kernel<1>,
                             cudaFuncAttributeMaxDynamicSharedMemorySize, SMEM_BYTES);
        cudaFuncSetAttribute(gemm_kernel<0>,
                             cudaFuncAttributeMaxDynamicSharedMemorySize, SMEM_BYTES);
        smem_set = 1;
    }

    init_kernel<<<64, 256>>>(edge, Wl, Wr);
    histogram_kernel<<<HBLOCKS, 256>>>(edge, x);
    scan_kernel<<<NSB, SBLK>>>();
    scatter_kernel<<<HBLOCKS, 256>>>(edge);

    int gblocks = (N_NODES + GNPB - 1) / GNPB;
    int mblocks = (N_NODES + NPB - 1) / NPB;

    __half* x16 = nullptr; __half* h16a = nullptr; __half* h16b = nullptr;
    __half* agg16 = nullptr;
    cudaGetSymbolAddress((void**)&x16, g_x16);
    cudaGetSymbolAddress((void**)&h16a, g_h16a);
    cudaGetSymbolAddress((void**)&h16b, g_h16b);
    cudaGetSymbolAddress((void**)&agg16, g_agg16);

    // layer 1
    gather16_kernel<<<gblocks, GTPB>>>(x16, agg16);
    gemm_kernel<1><<<mblocks, TPB, SMEM_BYTES>>>(agg16, x16, h16a, bl, 0);
    // layer 2
    gather16_kernel<<<gblocks, GTPB>>>(h16a, agg16);
    gemm_kernel<1><<<mblocks, TPB, SMEM_BYTES>>>(agg16, h16a, h16b, bl, 1);
    // layer 3
    gather16_kernel<<<gblocks, GTPB>>>(h16b, agg16);
    gemm_kernel<1><<<mblocks, TPB, SMEM_BYTES>>>(agg16, h16b, h16a, bl, 2);
    // layer 4: fp32 out
    gather16_kernel<<<gblocks, GTPB>>>(h16a, agg16);
    gemm_kernel<0><<<mblocks, TPB, SMEM_BYTES>>>(agg16, h16a, out, bl, 3);
}